// round 7
// baseline (speedup 1.0000x reference)
#include <cuda_runtime.h>
#include <cstdint>
#include <math.h>

#define BATCH 4
#define SEQ 2048
#define CH 768
#define NHEADS 12
#define HD 64
#define MTOT (BATCH * SEQ)   // 8192
#define C3 (3 * CH)          // 2304

// Scratch (allocation-free contract)
__device__ float g_x[(size_t)MTOT * CH];       // tf32-rounded x
__device__ float g_qkv[(size_t)MTOT * C3];     // tf32-rounded qkv
__device__ float g_att[(size_t)MTOT * CH];     // tf32-rounded attn out
__device__ float g_wqkvT[(size_t)C3 * CH];     // Wqkv^T, tf32-rounded
__device__ float g_wprojT[(size_t)CH * CH];    // Wproj^T, tf32-rounded

__device__ __forceinline__ uint32_t smem_u32(const void* p) {
    uint32_t a;
    asm("{ .reg .u64 t; cvta.to.shared.u64 t, %1; cvt.u32.u64 %0, t; }"
        : "=r"(a) : "l"(p));
    return a;
}
__device__ __forceinline__ float f2tf(float x) {
    unsigned u;
    asm("cvt.rna.tf32.f32 %0, %1;" : "=r"(u) : "f"(x));
    return __uint_as_float(u);
}
#define CP16(dst, src) \
    asm volatile("cp.async.cg.shared.global [%0], [%1], 16;" \
                 :: "r"(dst), "l"(src) : "memory")
#define CP_COMMIT() asm volatile("cp.async.commit_group;" ::: "memory")
#define CP_WAIT(n)  asm volatile("cp.async.wait_group %0;" :: "n"(n) : "memory")

// m16n8k8 tf32 mma, fp32 accumulate in-place.
__device__ __forceinline__ void mma8(float* c, const unsigned* a,
                                     unsigned b0, unsigned b1) {
    asm volatile(
        "mma.sync.aligned.m16n8k8.row.col.f32.tf32.tf32.f32 "
        "{%0,%1,%2,%3}, {%4,%5,%6,%7}, {%8,%9}, {%0,%1,%2,%3};"
        : "+f"(c[0]), "+f"(c[1]), "+f"(c[2]), "+f"(c[3])
        : "r"(a[0]), "r"(a[1]), "r"(a[2]), "r"(a[3]), "r"(b0), "r"(b1));
}
// ldmatrix x4 on 32-bit data (each m8n8.b16 matrix == one 8x4 tile of b32)
__device__ __forceinline__ void ldsm4(unsigned& r0, unsigned& r1,
                                      unsigned& r2, unsigned& r3,
                                      uint32_t addr) {
    asm volatile("ldmatrix.sync.aligned.m8n8.x4.shared.b16 {%0,%1,%2,%3}, [%4];"
                 : "=r"(r0), "=r"(r1), "=r"(r2), "=r"(r3) : "r"(addr));
}

// ---------------------------------------------------------------------------
// Prepass: round x to tf32
// ---------------------------------------------------------------------------
__global__ __launch_bounds__(256) void round_kernel(
    const float* __restrict__ in, float* __restrict__ outp)
{
    const int idx = blockIdx.x * 256 + threadIdx.x;
    float4 v = ((const float4*)in)[idx];
    float4 o = { f2tf(v.x), f2tf(v.y), f2tf(v.z), f2tf(v.w) };
    ((float4*)outp)[idx] = o;
}

// ---------------------------------------------------------------------------
// Weight transpose with tf32 rounding: Wt[n][k] = round(W[k][n])
// ---------------------------------------------------------------------------
__global__ __launch_bounds__(256) void transpose_kernel(
    const float* __restrict__ W, float* __restrict__ Wt, int R, int Cc)
{
    __shared__ float t[32][33];
    const int bx = blockIdx.x * 32, by = blockIdx.y * 32;
    const int x = threadIdx.x & 31, y4 = (threadIdx.x >> 5) * 4;
    #pragma unroll
    for (int j = 0; j < 4; j++)
        t[y4 + j][x] = W[(long)(by + y4 + j) * Cc + bx + x];
    __syncthreads();
    #pragma unroll
    for (int j = 0; j < 4; j++)
        Wt[(long)(bx + y4 + j) * R + by + x] = f2tf(t[x][y4 + j]);
}

// ---------------------------------------------------------------------------
// tf32 mma.sync GEMM + bias, ldmatrix feed + fragment software pipeline.
// 128x128 CTA tile, BK=32, 256 threads (8 warps 4x2, warp tile 32x64),
// cp.async double-buffered, 2 CTAs/SM.
// ---------------------------------------------------------------------------
#define GSTRIDE 36
#define GTILE (128 * GSTRIDE)

template <bool ROUND>
__global__ __launch_bounds__(256, 2) void gemm_tc(
    const float* __restrict__ A, const float* __restrict__ Bt,
    const float* __restrict__ bias, float* __restrict__ C,
    int M, int N, int K)
{
    extern __shared__ float gsm[];
    const int tid = threadIdx.x;
    const int lane = tid & 31, wid = tid >> 5;
    const int g = lane >> 2, tq = lane & 3;
    const int wm = (wid & 3) * 32, wn = (wid >> 2) * 64;
    const int bm = blockIdx.y * 128, bn = blockIdx.x * 128;
    const int sr = tid >> 3, sc4 = (tid & 7) * 4;

    const uint32_t sbase = smem_u32(gsm);
    const uint32_t a_base0 = sbase +
        ((wm + (lane & 15)) * GSTRIDE + (lane >> 4) * 4) * 4;
    const uint32_t b_base0 = sbase + GTILE * 4 +
        ((wn + (lane & 7) + (lane >> 4) * 8) * GSTRIDE + ((lane & 8) ? 4 : 0)) * 4;

    float acc[2][8][4];
    #pragma unroll
    for (int mt = 0; mt < 2; mt++)
        #pragma unroll
        for (int nt = 0; nt < 8; nt++)
            #pragma unroll
            for (int j = 0; j < 4; j++) acc[mt][nt][j] = 0.f;

    const int NK = K / 32;
    auto issue = [&](int kt, int b) {
        float* As = gsm + b * 2 * GTILE;
        float* Bs = As + GTILE;
        const int k0 = kt * 32;
        #pragma unroll
        for (int i = 0; i < 4; i++) {
            int r = sr + 32 * i;
            CP16(smem_u32(As + r * GSTRIDE + sc4),
                 A + (long)(bm + r) * K + k0 + sc4);
            CP16(smem_u32(Bs + r * GSTRIDE + sc4),
                 Bt + (long)(bn + r) * K + k0 + sc4);
        }
        CP_COMMIT();
    };

    issue(0, 0);
    for (int kt = 0; kt < NK; kt++) {
        const int buf = kt & 1;
        if (kt + 1 < NK) { issue(kt + 1, buf ^ 1); CP_WAIT(1); }
        else             { CP_WAIT(0); }
        __syncthreads();

        const uint32_t a_buf = a_base0 + buf * 2 * GTILE * 4;
        const uint32_t b_buf = b_base0 + buf * 2 * GTILE * 4;

        // preload fragments for ks=0
        unsigned af[2][4], bf[4][4];
        ldsm4(af[0][0], af[0][1], af[0][2], af[0][3], a_buf);
        ldsm4(af[1][0], af[1][1], af[1][2], af[1][3], a_buf + 16 * GSTRIDE * 4);
        #pragma unroll
        for (int p = 0; p < 4; p++)
            ldsm4(bf[p][0], bf[p][1], bf[p][2], bf[p][3],
                  b_buf + p * 16 * GSTRIDE * 4);

        #pragma unroll
        for (int ks = 0; ks < 4; ks++) {
            unsigned an[2][4], bn[4][4];
            if (ks < 3) {   // prefetch next k-step fragments
                ldsm4(an[0][0], an[0][1], an[0][2], an[0][3],
                      a_buf + (ks + 1) * 32);
                ldsm4(an[1][0], an[1][1], an[1][2], an[1][3],
                      a_buf + 16 * GSTRIDE * 4 + (ks + 1) * 32);
                #pragma unroll
                for (int p = 0; p < 4; p++)
                    ldsm4(bn[p][0], bn[p][1], bn[p][2], bn[p][3],
                          b_buf + p * 16 * GSTRIDE * 4 + (ks + 1) * 32);
            }
            #pragma unroll
            for (int p = 0; p < 4; p++) {
                mma8(acc[0][2 * p],     af[0], bf[p][0], bf[p][1]);
                mma8(acc[1][2 * p],     af[1], bf[p][0], bf[p][1]);
                mma8(acc[0][2 * p + 1], af[0], bf[p][2], bf[p][3]);
                mma8(acc[1][2 * p + 1], af[1], bf[p][2], bf[p][3]);
            }
            if (ks < 3) {
                #pragma unroll
                for (int j = 0; j < 4; j++) {
                    af[0][j] = an[0][j]; af[1][j] = an[1][j];
                    #pragma unroll
                    for (int p = 0; p < 4; p++) bf[p][j] = bn[p][j];
                }
            }
        }
        __syncthreads();
    }

    #pragma unroll
    for (int mt = 0; mt < 2; mt++) {
        const long r0 = bm + wm + mt * 16 + g;
        #pragma unroll
        for (int nt = 0; nt < 8; nt++) {
            const int col = bn + wn + nt * 8 + 2 * tq;
            const float bz0 = bias[col], bz1 = bias[col + 1];
            float2 v0 = { acc[mt][nt][0] + bz0, acc[mt][nt][1] + bz1 };
            float2 v1 = { acc[mt][nt][2] + bz0, acc[mt][nt][3] + bz1 };
            if (ROUND) {
                v0.x = f2tf(v0.x); v0.y = f2tf(v0.y);
                v1.x = f2tf(v1.x); v1.y = f2tf(v1.y);
            }
            *(float2*)(C + r0 * N + col)       = v0;
            *(float2*)(C + (r0 + 8) * N + col) = v1;
        }
    }
}

// ---------------------------------------------------------------------------
// Flash attention: Br=128, Bc=64, 256 threads (8 warps, 16 rows/warp),
// 2 CTAs/SM (16 warps/SM). ldmatrix Q/K/P, scalar-LDS V. Base-2 softmax.
// Smem: Q 128x68 | P 128x68 | K 64x68 | V 64x72 = 105472 B.
// ---------------------------------------------------------------------------
#define QS_OFF 0
#define PS_OFF (128 * 68)
#define KS_OFF (2 * 128 * 68)
#define VS_OFF (2 * 128 * 68 + 64 * 68)
#define FL_WORDS (2 * 128 * 68 + 64 * 68 + 64 * 72)   // 105472 B

__global__ __launch_bounds__(256, 2) void flash_tf32()
{
    extern __shared__ float sm[];
    float* Qs = sm + QS_OFF;
    float* Ps = sm + PS_OFF;
    float* Ks = sm + KS_OFF;
    float* Vs = sm + VS_OFF;

    const int tid = threadIdx.x;
    const int lane = tid & 31, w = tid >> 5;
    const int g = lane >> 2, tq = lane & 3;
    const int b = blockIdx.y / NHEADS, h = blockIdx.y % NHEADS;
    const int q0 = blockIdx.x * 128;
    const long rowbase = (long)b * SEQ;
    const float kscale = 0.125f * 1.44269504089f;   // 1/sqrt(d) * log2(e)

    // ldmatrix base addresses: warp owns rows [16w, 16w+16)
    const uint32_t q_base = smem_u32(Qs) +
        ((w * 16 + (lane & 15)) * 68 + (lane >> 4) * 4) * 4;
    const uint32_t p_base = smem_u32(Ps) +
        ((w * 16 + (lane & 15)) * 68 + (lane >> 4) * 4) * 4;
    const uint32_t k_base = smem_u32(Ks) +
        (((lane & 7) + (lane >> 4) * 8) * 68 + ((lane & 8) ? 4 : 0)) * 4;

    // Stage Q (scale folded, re-rounded to tf32): 2048 float4 / 256 thr
    #pragma unroll
    for (int i = 0; i < 8; i++) {
        int idx = tid + 256 * i;
        int r = idx >> 4, c4 = (idx & 15) * 4;
        float4 v = *(const float4*)&g_qkv[(rowbase + q0 + r) * C3 + h * HD + c4];
        float* d = Qs + r * 68 + c4;
        d[0] = f2tf(v.x * kscale); d[1] = f2tf(v.y * kscale);
        d[2] = f2tf(v.z * kscale); d[3] = f2tf(v.w * kscale);
    }

    float o[8][4];
    float m0 = -1e30f, m1 = -1e30f, l0 = 0.f, l1 = 0.f;
    #pragma unroll
    for (int nt = 0; nt < 8; nt++)
        #pragma unroll
        for (int j = 0; j < 4; j++) o[nt][j] = 0.f;

    for (int k0 = 0; k0 < SEQ; k0 += 64) {
        __syncthreads();
        // stage K,V: 1024 float4 each / 256 thr
        #pragma unroll
        for (int i = 0; i < 4; i++) {
            int idx = tid + 256 * i;
            int r = idx >> 4, c4 = (idx & 15) * 4;
            long gb = (rowbase + k0 + r) * C3 + h * HD + c4;
            CP16(smem_u32(Ks + r * 68 + c4), &g_qkv[gb + CH]);
            CP16(smem_u32(Vs + r * 72 + c4), &g_qkv[gb + 2 * CH]);
        }
        CP_COMMIT();
        CP_WAIT(0);
        __syncthreads();

        // S = Q @ K^T  (warp rows [16w, 16w+16), 64 kv cols)
        float s[8][4];
        #pragma unroll
        for (int nt = 0; nt < 8; nt++)
            #pragma unroll
            for (int j = 0; j < 4; j++) s[nt][j] = 0.f;
        #pragma unroll
        for (int ks = 0; ks < 8; ks++) {
            unsigned af[4];
            ldsm4(af[0], af[1], af[2], af[3], q_base + ks * 32);
            #pragma unroll
            for (int ntp = 0; ntp < 4; ntp++) {
                unsigned b0, b1, c0, c1;
                ldsm4(b0, b1, c0, c1, k_base + ntp * 16 * 68 * 4 + ks * 32);
                mma8(s[2 * ntp],     af, b0, b1);
                mma8(s[2 * ntp + 1], af, c0, c1);
            }
        }

        // Online softmax (base-2): rows 16w+g (s[..][0,1]), 16w+g+8 (s[..][2,3])
        float mx0 = -1e30f, mx1 = -1e30f;
        #pragma unroll
        for (int nt = 0; nt < 8; nt++) {
            mx0 = fmaxf(mx0, fmaxf(s[nt][0], s[nt][1]));
            mx1 = fmaxf(mx1, fmaxf(s[nt][2], s[nt][3]));
        }
        mx0 = fmaxf(mx0, __shfl_xor_sync(0xffffffffu, mx0, 1));
        mx0 = fmaxf(mx0, __shfl_xor_sync(0xffffffffu, mx0, 2));
        mx1 = fmaxf(mx1, __shfl_xor_sync(0xffffffffu, mx1, 1));
        mx1 = fmaxf(mx1, __shfl_xor_sync(0xffffffffu, mx1, 2));
        const float mn0 = fmaxf(m0, mx0), mn1 = fmaxf(m1, mx1);
        const float cr0 = exp2f(m0 - mn0), cr1 = exp2f(m1 - mn1);
        float rs0 = 0.f, rs1 = 0.f;
        #pragma unroll
        for (int nt = 0; nt < 8; nt++) {
            s[nt][0] = exp2f(s[nt][0] - mn0); rs0 += s[nt][0];
            s[nt][1] = exp2f(s[nt][1] - mn0); rs0 += s[nt][1];
            s[nt][2] = exp2f(s[nt][2] - mn1); rs1 += s[nt][2];
            s[nt][3] = exp2f(s[nt][3] - mn1); rs1 += s[nt][3];
        }
        rs0 += __shfl_xor_sync(0xffffffffu, rs0, 1);
        rs0 += __shfl_xor_sync(0xffffffffu, rs0, 2);
        rs1 += __shfl_xor_sync(0xffffffffu, rs1, 1);
        rs1 += __shfl_xor_sync(0xffffffffu, rs1, 2);
        l0 = l0 * cr0 + rs0;  l1 = l1 * cr1 + rs1;
        m0 = mn0;  m1 = mn1;
        #pragma unroll
        for (int nt = 0; nt < 8; nt++) {
            o[nt][0] *= cr0; o[nt][1] *= cr0;
            o[nt][2] *= cr1; o[nt][3] *= cr1;
        }

        // Store P (warp-private 16-row strip), tf32-rounded, STS.64
        {
            const int pr = w * 16 + g;
            #pragma unroll
            for (int nt = 0; nt < 8; nt++) {
                const int pc = nt * 8 + 2 * tq;
                float2 p0 = { f2tf(s[nt][0]), f2tf(s[nt][1]) };
                float2 p1 = { f2tf(s[nt][2]), f2tf(s[nt][3]) };
                *(float2*)(Ps + pr * 68 + pc)       = p0;
                *(float2*)(Ps + (pr + 8) * 68 + pc) = p1;
            }
        }
        __syncwarp();

        // O += P @ V  (P via ldmatrix, V scalar LDS)
        const unsigned* Vu = (const unsigned*)Vs;
        #pragma unroll
        for (int ks = 0; ks < 8; ks++) {
            const int kb = ks * 8;
            unsigned af[4];
            ldsm4(af[0], af[1], af[2], af[3], p_base + ks * 32);
            #pragma unroll
            for (int nt = 0; nt < 8; nt++) {
                int c = nt * 8 + g;
                unsigned b0 = Vu[(kb + tq) * 72 + c];
                unsigned b1 = Vu[(kb + tq + 4) * 72 + c];
                mma8(o[nt], af, b0, b1);
            }
        }
    }

    // Epilogue: normalize, round to tf32 (feeds proj GEMM), write
    {
        const float inv0 = 1.f / l0, inv1 = 1.f / l1;
        const long r0 = rowbase + q0 + w * 16 + g;
        #pragma unroll
        for (int nt = 0; nt < 8; nt++) {
            const int col = h * HD + nt * 8 + 2 * tq;
            float2 v0 = { f2tf(o[nt][0] * inv0), f2tf(o[nt][1] * inv0) };
            float2 v1 = { f2tf(o[nt][2] * inv1), f2tf(o[nt][3] * inv1) };
            *(float2*)(g_att + r0 * CH + col)       = v0;
            *(float2*)(g_att + (r0 + 8) * CH + col) = v1;
        }
    }
}

// ---------------------------------------------------------------------------
extern "C" void kernel_launch(void* const* d_in, const int* in_sizes, int n_in,
                              void* d_out, int out_size)
{
    const float* x     = (const float*)d_in[0];
    const float* Wqkv  = (const float*)d_in[1];
    const float* bqkv  = (const float*)d_in[2];
    const float* Wproj = (const float*)d_in[3];
    const float* bproj = (const float*)d_in[4];
    float* out = (float*)d_out;

    float *xr, *qkv_ptr, *att_ptr, *wqkvT, *wprojT;
    cudaGetSymbolAddress((void**)&xr, g_x);
    cudaGetSymbolAddress((void**)&qkv_ptr, g_qkv);
    cudaGetSymbolAddress((void**)&att_ptr, g_att);
    cudaGetSymbolAddress((void**)&wqkvT, g_wqkvT);
    cudaGetSymbolAddress((void**)&wprojT, g_wprojT);

    static int smem_set = 0;
    const int gemm_smem  = 4 * GTILE * sizeof(float);     // 73728 B
    const int flash_smem = FL_WORDS * sizeof(float);      // 105472 B
    if (!smem_set) {
        cudaFuncSetAttribute(gemm_tc<true>,
            cudaFuncAttributeMaxDynamicSharedMemorySize, gemm_smem);
        cudaFuncSetAttribute(gemm_tc<false>,
            cudaFuncAttributeMaxDynamicSharedMemorySize, gemm_smem);
        cudaFuncSetAttribute(flash_tf32,
            cudaFuncAttributeMaxDynamicSharedMemorySize, flash_smem);
        smem_set = 1;
    }

    // Pre-round x; transpose + round weights
    round_kernel<<<(MTOT * CH) / 1024, 256>>>(x, xr);
    transpose_kernel<<<dim3(C3 / 32, CH / 32), 256>>>(Wqkv, wqkvT, CH, C3);
    transpose_kernel<<<dim3(CH / 32, CH / 32), 256>>>(Wproj, wprojT, CH, CH);

    // QKV projection (tf32-rounded output)
    gemm_tc<true><<<dim3(C3 / 128, MTOT / 128), 256, gemm_smem>>>(
        xr, wqkvT, bqkv, qkv_ptr, MTOT, C3, CH);
    // Flash attention (Br=128, 256 threads, 2 CTAs/SM)
    flash_tf32<<<dim3(SEQ / 128, BATCH * NHEADS), 256, flash_smem>>>();
    // Output projection (full fp32 output)
    gemm_tc<false><<<dim3(CH / 128, MTOT / 128), 256, gemm_smem>>>(
        att_ptr, wprojT, bproj, out, MTOT, CH, CH);
}

// round 9
// speedup vs baseline: 1.9412x; 1.9412x over previous
#include <cuda_runtime.h>
#include <cuda_fp16.h>
#include <cstdint>
#include <math.h>

#define BATCH 4
#define SEQ 2048
#define CH 768
#define NHEADS 12
#define HD 64
#define MTOT (BATCH * SEQ)   // 8192
#define C3 (3 * CH)          // 2304

// Scratch (allocation-free contract) — all fp16
__device__ __half g_x[(size_t)MTOT * CH];
__device__ __half g_qkv[(size_t)MTOT * C3];
__device__ __half g_att[(size_t)MTOT * CH];
__device__ __half g_wqkvT[(size_t)C3 * CH];
__device__ __half g_wprojT[(size_t)CH * CH];

__device__ __forceinline__ uint32_t smem_u32(const void* p) {
    uint32_t a;
    asm("{ .reg .u64 t; cvta.to.shared.u64 t, %1; cvt.u32.u64 %0, t; }"
        : "=r"(a) : "l"(p));
    return a;
}
#define CP16(dst, src) \
    asm volatile("cp.async.cg.shared.global [%0], [%1], 16;" \
                 :: "r"(dst), "l"(src) : "memory")
#define CP_COMMIT() asm volatile("cp.async.commit_group;" ::: "memory")
#define CP_WAIT(n)  asm volatile("cp.async.wait_group %0;" :: "n"(n) : "memory")

// m16n8k16 fp16 mma, fp32 accumulate in-place.
__device__ __forceinline__ void mma16(float* c, const unsigned* a,
                                      unsigned b0, unsigned b1) {
    asm volatile(
        "mma.sync.aligned.m16n8k16.row.col.f32.f16.f16.f32 "
        "{%0,%1,%2,%3}, {%4,%5,%6,%7}, {%8,%9}, {%0,%1,%2,%3};"
        : "+f"(c[0]), "+f"(c[1]), "+f"(c[2]), "+f"(c[3])
        : "r"(a[0]), "r"(a[1]), "r"(a[2]), "r"(a[3]), "r"(b0), "r"(b1));
}
__device__ __forceinline__ void ldsm4(unsigned& r0, unsigned& r1,
                                      unsigned& r2, unsigned& r3,
                                      uint32_t addr) {
    asm volatile("ldmatrix.sync.aligned.m8n8.x4.shared.b16 {%0,%1,%2,%3}, [%4];"
                 : "=r"(r0), "=r"(r1), "=r"(r2), "=r"(r3) : "r"(addr));
}
__device__ __forceinline__ void ldsm4t(unsigned& r0, unsigned& r1,
                                       unsigned& r2, unsigned& r3,
                                       uint32_t addr) {
    asm volatile("ldmatrix.sync.aligned.m8n8.x4.trans.shared.b16 {%0,%1,%2,%3}, [%4];"
                 : "=r"(r0), "=r"(r1), "=r"(r2), "=r"(r3) : "r"(addr));
}

// ---------------------------------------------------------------------------
// Prepass: round x to fp16
// ---------------------------------------------------------------------------
__global__ __launch_bounds__(256) void round_kernel(
    const float* __restrict__ in, __half* __restrict__ outp)
{
    const int idx = blockIdx.x * 256 + threadIdx.x;
    float4 v = ((const float4*)in)[idx];
    __half2 h0 = __floats2half2_rn(v.x, v.y);
    __half2 h1 = __floats2half2_rn(v.z, v.w);
    uint2 o = { *(unsigned*)&h0, *(unsigned*)&h1 };
    ((uint2*)outp)[idx] = o;
}

// ---------------------------------------------------------------------------
// Weight transpose to fp16: Wt[n][k] = half(W[k][n])
// ---------------------------------------------------------------------------
__global__ __launch_bounds__(256) void transpose_kernel(
    const float* __restrict__ W, __half* __restrict__ Wt, int R, int Cc)
{
    __shared__ float t[32][33];
    const int bx = blockIdx.x * 32, by = blockIdx.y * 32;
    const int x = threadIdx.x & 31, y4 = (threadIdx.x >> 5) * 4;
    #pragma unroll
    for (int j = 0; j < 4; j++)
        t[y4 + j][x] = W[(long)(by + y4 + j) * Cc + bx + x];
    __syncthreads();
    #pragma unroll
    for (int j = 0; j < 4; j++)
        Wt[(long)(bx + y4 + j) * R + by + x] = __float2half_rn(t[x][y4 + j]);
}

// ---------------------------------------------------------------------------
// fp16 mma.sync GEMM + bias: C[M,N] = A[M,K] @ Bt[N,K]^T + bias
// 128x128 CTA tile, BK=64 halves, 256 threads (8 warps 4x2, warp 32x64),
// cp.async double-buffered, 2 CTAs/SM, ldmatrix feed.
// ---------------------------------------------------------------------------
#define HS 72
#define HTILE (128 * HS)   // halves per operand tile

template <bool HALF_OUT>
__global__ __launch_bounds__(256, 2) void gemm_fp16(
    const __half* __restrict__ A, const __half* __restrict__ Bt,
    const float* __restrict__ bias, void* __restrict__ Cout,
    int M, int N, int K)
{
    extern __shared__ __half hsm[];
    const int tid = threadIdx.x;
    const int lane = tid & 31, wid = tid >> 5;
    const int g = lane >> 2, tq = lane & 3;
    const int wm = (wid & 3) * 32, wn = (wid >> 2) * 64;
    const int bm = blockIdx.y * 128, bn = blockIdx.x * 128;
    const int sr = tid >> 3, sc8 = (tid & 7) * 8;

    const uint32_t sbase = smem_u32(hsm);
    const uint32_t a_base0 = sbase +
        ((wm + (lane & 15)) * HS + (lane >> 4) * 8) * 2;
    const uint32_t b_base0 = sbase + HTILE * 2 +
        ((wn + (lane & 7) + (lane >> 4) * 8) * HS + ((lane >> 3) & 1) * 8) * 2;

    float acc[2][8][4];
    #pragma unroll
    for (int mt = 0; mt < 2; mt++)
        #pragma unroll
        for (int nt = 0; nt < 8; nt++)
            #pragma unroll
            for (int j = 0; j < 4; j++) acc[mt][nt][j] = 0.f;

    const int NK = K / 64;
    auto issue = [&](int kt, int b) {
        __half* As = hsm + b * 2 * HTILE;
        __half* Bs = As + HTILE;
        const int k0 = kt * 64;
        #pragma unroll
        for (int i = 0; i < 4; i++) {
            int r = sr + 32 * i;
            CP16(smem_u32(As + r * HS + sc8),
                 A + (long)(bm + r) * K + k0 + sc8);
            CP16(smem_u32(Bs + r * HS + sc8),
                 Bt + (long)(bn + r) * K + k0 + sc8);
        }
        CP_COMMIT();
    };

    issue(0, 0);
    for (int kt = 0; kt < NK; kt++) {
        const int buf = kt & 1;
        if (kt + 1 < NK) { issue(kt + 1, buf ^ 1); CP_WAIT(1); }
        else             { CP_WAIT(0); }
        __syncthreads();

        const uint32_t a_buf = a_base0 + buf * 2 * HTILE * 2;
        const uint32_t b_buf = b_base0 + buf * 2 * HTILE * 2;
        #pragma unroll
        for (int ks = 0; ks < 4; ks++) {     // 4 x k16 = 64 halves
            unsigned af[2][4];
            ldsm4(af[0][0], af[0][1], af[0][2], af[0][3], a_buf + ks * 32);
            ldsm4(af[1][0], af[1][1], af[1][2], af[1][3],
                  a_buf + 16 * HS * 2 + ks * 32);
            #pragma unroll
            for (int p = 0; p < 4; p++) {
                unsigned b0, b1, c0, c1;
                ldsm4(b0, b1, c0, c1, b_buf + p * 16 * HS * 2 + ks * 32);
                mma16(acc[0][2 * p],     af[0], b0, b1);
                mma16(acc[1][2 * p],     af[1], b0, b1);
                mma16(acc[0][2 * p + 1], af[0], c0, c1);
                mma16(acc[1][2 * p + 1], af[1], c0, c1);
            }
        }
        __syncthreads();
    }

    #pragma unroll
    for (int mt = 0; mt < 2; mt++) {
        const long r0 = bm + wm + mt * 16 + g;
        #pragma unroll
        for (int nt = 0; nt < 8; nt++) {
            const int col = bn + wn + nt * 8 + 2 * tq;
            const float bz0 = bias[col], bz1 = bias[col + 1];
            if (HALF_OUT) {
                __half* C = (__half*)Cout;
                __half2 v0 = __floats2half2_rn(acc[mt][nt][0] + bz0,
                                               acc[mt][nt][1] + bz1);
                __half2 v1 = __floats2half2_rn(acc[mt][nt][2] + bz0,
                                               acc[mt][nt][3] + bz1);
                *(__half2*)(C + r0 * N + col)       = v0;
                *(__half2*)(C + (r0 + 8) * N + col) = v1;
            } else {
                float* C = (float*)Cout;
                float2 v0 = { acc[mt][nt][0] + bz0, acc[mt][nt][1] + bz1 };
                float2 v1 = { acc[mt][nt][2] + bz0, acc[mt][nt][3] + bz1 };
                *(float2*)(C + r0 * N + col)       = v0;
                *(float2*)(C + (r0 + 8) * N + col) = v1;
            }
        }
    }
}

// ---------------------------------------------------------------------------
// Flash attention fp16: Br=128, Bc=64, 128 threads (4 warps), 2 CTAs/SM,
// warp rows [32w, 32w+32). Q/K/P ldmatrix, V ldmatrix.trans.
// Base-2 online softmax in f32, scale*log2e folded into Q staging (f32 path).
// ---------------------------------------------------------------------------
#define QS_OFF 0
#define PS_OFF (128 * HS)
#define KS_OFF (2 * 128 * HS)
#define VS_OFF (2 * 128 * HS + 64 * HS)
#define FL_HALVES (2 * 128 * HS + 2 * 64 * HS)   // 27648 halves = 55296 B

__global__ __launch_bounds__(128, 2) void flash_fp16()
{
    extern __shared__ __half fsm[];
    __half* Qs = fsm + QS_OFF;
    __half* Ps = fsm + PS_OFF;
    __half* Ks = fsm + KS_OFF;
    __half* Vs = fsm + VS_OFF;

    const int tid = threadIdx.x;
    const int lane = tid & 31, w = tid >> 5;
    const int g = lane >> 2, tq = lane & 3;
    const int b = blockIdx.y / NHEADS, h = blockIdx.y % NHEADS;
    const int q0 = blockIdx.x * 128;
    const long rowbase = (long)b * SEQ;
    const float kscale = 0.125f * 1.44269504089f;   // 1/sqrt(d) * log2(e)

    const uint32_t q_base = smem_u32(Qs) +
        ((w * 32 + (lane & 15)) * HS + (lane >> 4) * 8) * 2;
    const uint32_t p_base = smem_u32(Ps) +
        ((w * 32 + (lane & 15)) * HS + (lane >> 4) * 8) * 2;
    const uint32_t k_base = smem_u32(Ks) +
        (((lane & 7) + (lane >> 4) * 8) * HS + ((lane >> 3) & 1) * 8) * 2;
    const uint32_t v_base = smem_u32(Vs) +
        (((lane & 7) + ((lane >> 3) & 1) * 8) * HS + (lane >> 4) * 8) * 2;

    // Stage Q: 128 rows x 8 chunks of 8 halves (uint4 = FULL 16B chunk).
    // Scale applied through f32 (keeps kscale exact), rounded back to fp16.
    #pragma unroll
    for (int i = 0; i < 8; i++) {
        int idx = tid + 128 * i;
        int r = idx >> 3, c8 = (idx & 7) * 8;
        uint4 v = *(const uint4*)&g_qkv[(rowbase + q0 + r) * C3 + h * HD + c8];
        __half2* hp = (__half2*)&v;
        #pragma unroll
        for (int j = 0; j < 4; j++) {
            float2 f = __half22float2(hp[j]);
            hp[j] = __floats2half2_rn(f.x * kscale, f.y * kscale);
        }
        *(uint4*)(Qs + r * HS + c8) = v;
    }

    float o[2][8][4];
    float m_i[2][2], l_i[2][2];
    #pragma unroll
    for (int mt = 0; mt < 2; mt++) {
        m_i[mt][0] = m_i[mt][1] = -1e30f;
        l_i[mt][0] = l_i[mt][1] = 0.f;
        #pragma unroll
        for (int nt = 0; nt < 8; nt++)
            #pragma unroll
            for (int j = 0; j < 4; j++) o[mt][nt][j] = 0.f;
    }

    for (int k0 = 0; k0 < SEQ; k0 += 64) {
        __syncthreads();
        #pragma unroll
        for (int i = 0; i < 4; i++) {
            int idx = tid + 128 * i;
            int r = idx >> 3, c8 = (idx & 7) * 8;
            long gb = (rowbase + k0 + r) * C3 + h * HD + c8;
            CP16(smem_u32(Ks + r * HS + c8), &g_qkv[gb + CH]);
            CP16(smem_u32(Vs + r * HS + c8), &g_qkv[gb + 2 * CH]);
        }
        CP_COMMIT();
        CP_WAIT(0);
        __syncthreads();

        // S = Q @ K^T  (4 x k16 over d=64)
        float s[2][8][4];
        #pragma unroll
        for (int mt = 0; mt < 2; mt++)
            #pragma unroll
            for (int nt = 0; nt < 8; nt++)
                #pragma unroll
                for (int j = 0; j < 4; j++) s[mt][nt][j] = 0.f;
        #pragma unroll
        for (int ks = 0; ks < 4; ks++) {
            unsigned af[2][4];
            ldsm4(af[0][0], af[0][1], af[0][2], af[0][3], q_base + ks * 32);
            ldsm4(af[1][0], af[1][1], af[1][2], af[1][3],
                  q_base + 16 * HS * 2 + ks * 32);
            #pragma unroll
            for (int p = 0; p < 4; p++) {
                unsigned b0, b1, c0, c1;
                ldsm4(b0, b1, c0, c1, k_base + p * 16 * HS * 2 + ks * 32);
                mma16(s[0][2 * p],     af[0], b0, b1);
                mma16(s[1][2 * p],     af[1], b0, b1);
                mma16(s[0][2 * p + 1], af[0], c0, c1);
                mma16(s[1][2 * p + 1], af[1], c0, c1);
            }
        }

        // Online softmax (base-2) per 16-row sub-tile
        #pragma unroll
        for (int mt = 0; mt < 2; mt++) {
            float mx0 = -1e30f, mx1 = -1e30f;
            #pragma unroll
            for (int nt = 0; nt < 8; nt++) {
                mx0 = fmaxf(mx0, fmaxf(s[mt][nt][0], s[mt][nt][1]));
                mx1 = fmaxf(mx1, fmaxf(s[mt][nt][2], s[mt][nt][3]));
            }
            mx0 = fmaxf(mx0, __shfl_xor_sync(0xffffffffu, mx0, 1));
            mx0 = fmaxf(mx0, __shfl_xor_sync(0xffffffffu, mx0, 2));
            mx1 = fmaxf(mx1, __shfl_xor_sync(0xffffffffu, mx1, 1));
            mx1 = fmaxf(mx1, __shfl_xor_sync(0xffffffffu, mx1, 2));
            const float mn0 = fmaxf(m_i[mt][0], mx0), mn1 = fmaxf(m_i[mt][1], mx1);
            const float cr0 = exp2f(m_i[mt][0] - mn0), cr1 = exp2f(m_i[mt][1] - mn1);
            float rs0 = 0.f, rs1 = 0.f;
            #pragma unroll
            for (int nt = 0; nt < 8; nt++) {
                s[mt][nt][0] = exp2f(s[mt][nt][0] - mn0); rs0 += s[mt][nt][0];
                s[mt][nt][1] = exp2f(s[mt][nt][1] - mn0); rs0 += s[mt][nt][1];
                s[mt][nt][2] = exp2f(s[mt][nt][2] - mn1); rs1 += s[mt][nt][2];
                s[mt][nt][3] = exp2f(s[mt][nt][3] - mn1); rs1 += s[mt][nt][3];
            }
            rs0 += __shfl_xor_sync(0xffffffffu, rs0, 1);
            rs0 += __shfl_xor_sync(0xffffffffu, rs0, 2);
            rs1 += __shfl_xor_sync(0xffffffffu, rs1, 1);
            rs1 += __shfl_xor_sync(0xffffffffu, rs1, 2);
            l_i[mt][0] = l_i[mt][0] * cr0 + rs0;
            l_i[mt][1] = l_i[mt][1] * cr1 + rs1;
            m_i[mt][0] = mn0; m_i[mt][1] = mn1;
            #pragma unroll
            for (int nt = 0; nt < 8; nt++) {
                o[mt][nt][0] *= cr0; o[mt][nt][1] *= cr0;
                o[mt][nt][2] *= cr1; o[mt][nt][3] *= cr1;
            }
            const int pr = w * 32 + mt * 16 + g;
            #pragma unroll
            for (int nt = 0; nt < 8; nt++) {
                const int pc = nt * 8 + 2 * tq;
                *(__half2*)(Ps + pr * HS + pc) =
                    __floats2half2_rn(s[mt][nt][0], s[mt][nt][1]);
                *(__half2*)(Ps + (pr + 8) * HS + pc) =
                    __floats2half2_rn(s[mt][nt][2], s[mt][nt][3]);
            }
        }
        __syncwarp();

        // O += P @ V  (4 x k16 over kv=64; V via ldmatrix.trans)
        #pragma unroll
        for (int ks = 0; ks < 4; ks++) {
            unsigned af[2][4];
            ldsm4(af[0][0], af[0][1], af[0][2], af[0][3], p_base + ks * 32);
            ldsm4(af[1][0], af[1][1], af[1][2], af[1][3],
                  p_base + 16 * HS * 2 + ks * 32);
            #pragma unroll
            for (int p = 0; p < 4; p++) {
                unsigned b0, b1, c0, c1;
                ldsm4t(b0, b1, c0, c1,
                       v_base + ks * 16 * HS * 2 + p * 16 * 2);
                mma16(o[0][2 * p],     af[0], b0, b1);
                mma16(o[1][2 * p],     af[1], b0, b1);
                mma16(o[0][2 * p + 1], af[0], c0, c1);
                mma16(o[1][2 * p + 1], af[1], c0, c1);
            }
        }
    }

    // Epilogue: normalize, store fp16 (feeds proj GEMM)
    #pragma unroll
    for (int mt = 0; mt < 2; mt++) {
        const float inv0 = 1.f / l_i[mt][0], inv1 = 1.f / l_i[mt][1];
        const long r0 = rowbase + q0 + w * 32 + mt * 16 + g;
        #pragma unroll
        for (int nt = 0; nt < 8; nt++) {
            const int col = h * HD + nt * 8 + 2 * tq;
            *(__half2*)(g_att + r0 * CH + col) =
                __floats2half2_rn(o[mt][nt][0] * inv0, o[mt][nt][1] * inv0);
            *(__half2*)(g_att + (r0 + 8) * CH + col) =
                __floats2half2_rn(o[mt][nt][2] * inv1, o[mt][nt][3] * inv1);
        }
    }
}

// ---------------------------------------------------------------------------
extern "C" void kernel_launch(void* const* d_in, const int* in_sizes, int n_in,
                              void* d_out, int out_size)
{
    const float* x     = (const float*)d_in[0];
    const float* Wqkv  = (const float*)d_in[1];
    const float* bqkv  = (const float*)d_in[2];
    const float* Wproj = (const float*)d_in[3];
    const float* bproj = (const float*)d_in[4];
    float* out = (float*)d_out;

    __half *xr, *qkv_ptr, *att_ptr, *wqkvT, *wprojT;
    cudaGetSymbolAddress((void**)&xr, g_x);
    cudaGetSymbolAddress((void**)&qkv_ptr, g_qkv);
    cudaGetSymbolAddress((void**)&att_ptr, g_att);
    cudaGetSymbolAddress((void**)&wqkvT, g_wqkvT);
    cudaGetSymbolAddress((void**)&wprojT, g_wprojT);

    static int smem_set = 0;
    const int gemm_smem  = 4 * HTILE * sizeof(__half);    // 73728 B
    const int flash_smem = FL_HALVES * sizeof(__half);    // 55296 B
    if (!smem_set) {
        cudaFuncSetAttribute(gemm_fp16<true>,
            cudaFuncAttributeMaxDynamicSharedMemorySize, gemm_smem);
        cudaFuncSetAttribute(gemm_fp16<false>,
            cudaFuncAttributeMaxDynamicSharedMemorySize, gemm_smem);
        cudaFuncSetAttribute(flash_fp16,
            cudaFuncAttributeMaxDynamicSharedMemorySize, flash_smem);
        smem_set = 1;
    }

    // Pre-round x to fp16; transpose weights to fp16
    round_kernel<<<(MTOT * CH) / 1024, 256>>>(x, xr);
    transpose_kernel<<<dim3(C3 / 32, CH / 32), 256>>>(Wqkv, wqkvT, CH, C3);
    transpose_kernel<<<dim3(CH / 32, CH / 32), 256>>>(Wproj, wprojT, CH, CH);

    // QKV projection (fp16 output)
    gemm_fp16<true><<<dim3(C3 / 128, MTOT / 128), 256, gemm_smem>>>(
        xr, wqkvT, bqkv, qkv_ptr, MTOT, C3, CH);
    // Flash attention
    flash_fp16<<<dim3(SEQ / 128, BATCH * NHEADS), 128, flash_smem>>>();
    // Output projection (fp32 output)
    gemm_fp16<false><<<dim3(CH / 128, MTOT / 128), 256, gemm_smem>>>(
        att_ptr, wprojT, bproj, out, MTOT, CH, CH);
}

// round 10
// speedup vs baseline: 1.9984x; 1.0294x over previous
#include <cuda_runtime.h>
#include <cuda_fp16.h>
#include <cstdint>
#include <math.h>

#define BATCH 4
#define SEQ 2048
#define CH 768
#define NHEADS 12
#define HD 64
#define MTOT (BATCH * SEQ)   // 8192
#define C3 (3 * CH)          // 2304

// Scratch (allocation-free contract) — all fp16
__device__ __half g_x[(size_t)MTOT * CH];
__device__ __half g_qkv[(size_t)MTOT * C3];
__device__ __half g_att[(size_t)MTOT * CH];
__device__ __half g_wqkvT[(size_t)C3 * CH];
__device__ __half g_wprojT[(size_t)CH * CH];

__device__ __forceinline__ uint32_t smem_u32(const void* p) {
    uint32_t a;
    asm("{ .reg .u64 t; cvta.to.shared.u64 t, %1; cvt.u32.u64 %0, t; }"
        : "=r"(a) : "l"(p));
    return a;
}
#define CP16(dst, src) \
    asm volatile("cp.async.cg.shared.global [%0], [%1], 16;" \
                 :: "r"(dst), "l"(src) : "memory")
#define CP_COMMIT() asm volatile("cp.async.commit_group;" ::: "memory")
#define CP_WAIT(n)  asm volatile("cp.async.wait_group %0;" :: "n"(n) : "memory")

// m16n8k16 fp16 mma, fp32 accumulate in-place.
__device__ __forceinline__ void mma16(float* c, const unsigned* a,
                                      unsigned b0, unsigned b1) {
    asm volatile(
        "mma.sync.aligned.m16n8k16.row.col.f32.f16.f16.f32 "
        "{%0,%1,%2,%3}, {%4,%5,%6,%7}, {%8,%9}, {%0,%1,%2,%3};"
        : "+f"(c[0]), "+f"(c[1]), "+f"(c[2]), "+f"(c[3])
        : "r"(a[0]), "r"(a[1]), "r"(a[2]), "r"(a[3]), "r"(b0), "r"(b1));
}
__device__ __forceinline__ void ldsm4(unsigned& r0, unsigned& r1,
                                      unsigned& r2, unsigned& r3,
                                      uint32_t addr) {
    asm volatile("ldmatrix.sync.aligned.m8n8.x4.shared.b16 {%0,%1,%2,%3}, [%4];"
                 : "=r"(r0), "=r"(r1), "=r"(r2), "=r"(r3) : "r"(addr));
}
__device__ __forceinline__ void ldsm4t(unsigned& r0, unsigned& r1,
                                       unsigned& r2, unsigned& r3,
                                       uint32_t addr) {
    asm volatile("ldmatrix.sync.aligned.m8n8.x4.trans.shared.b16 {%0,%1,%2,%3}, [%4];"
                 : "=r"(r0), "=r"(r1), "=r"(r2), "=r"(r3) : "r"(addr));
}

// ---------------------------------------------------------------------------
// Prepass: round x to fp16
// ---------------------------------------------------------------------------
__global__ __launch_bounds__(256) void round_kernel(
    const float* __restrict__ in, __half* __restrict__ outp)
{
    const int idx = blockIdx.x * 256 + threadIdx.x;
    float4 v = ((const float4*)in)[idx];
    __half2 h0 = __floats2half2_rn(v.x, v.y);
    __half2 h1 = __floats2half2_rn(v.z, v.w);
    uint2 o = { *(unsigned*)&h0, *(unsigned*)&h1 };
    ((uint2*)outp)[idx] = o;
}

// ---------------------------------------------------------------------------
// Weight transpose to fp16: Wt[n][k] = half(W[k][n])
// ---------------------------------------------------------------------------
__global__ __launch_bounds__(256) void transpose_kernel(
    const float* __restrict__ W, __half* __restrict__ Wt, int R, int Cc)
{
    __shared__ float t[32][33];
    const int bx = blockIdx.x * 32, by = blockIdx.y * 32;
    const int x = threadIdx.x & 31, y4 = (threadIdx.x >> 5) * 4;
    #pragma unroll
    for (int j = 0; j < 4; j++)
        t[y4 + j][x] = W[(long)(by + y4 + j) * Cc + bx + x];
    __syncthreads();
    #pragma unroll
    for (int j = 0; j < 4; j++)
        Wt[(long)(bx + y4 + j) * R + by + x] = __float2half_rn(t[x][y4 + j]);
}

// ---------------------------------------------------------------------------
// fp16 mma.sync GEMM + bias (unchanged from R9): C = A @ Bt^T + bias
// ---------------------------------------------------------------------------
#define HS 72
#define HTILE (128 * HS)   // halves per operand tile

template <bool HALF_OUT>
__global__ __launch_bounds__(256, 2) void gemm_fp16(
    const __half* __restrict__ A, const __half* __restrict__ Bt,
    const float* __restrict__ bias, void* __restrict__ Cout,
    int M, int N, int K)
{
    extern __shared__ __half hsm[];
    const int tid = threadIdx.x;
    const int lane = tid & 31, wid = tid >> 5;
    const int g = lane >> 2, tq = lane & 3;
    const int wm = (wid & 3) * 32, wn = (wid >> 2) * 64;
    const int bm = blockIdx.y * 128, bn = blockIdx.x * 128;
    const int sr = tid >> 3, sc8 = (tid & 7) * 8;

    const uint32_t sbase = smem_u32(hsm);
    const uint32_t a_base0 = sbase +
        ((wm + (lane & 15)) * HS + (lane >> 4) * 8) * 2;
    const uint32_t b_base0 = sbase + HTILE * 2 +
        ((wn + (lane & 7) + (lane >> 4) * 8) * HS + ((lane >> 3) & 1) * 8) * 2;

    float acc[2][8][4];
    #pragma unroll
    for (int mt = 0; mt < 2; mt++)
        #pragma unroll
        for (int nt = 0; nt < 8; nt++)
            #pragma unroll
            for (int j = 0; j < 4; j++) acc[mt][nt][j] = 0.f;

    const int NK = K / 64;
    auto issue = [&](int kt, int b) {
        __half* As = hsm + b * 2 * HTILE;
        __half* Bs = As + HTILE;
        const int k0 = kt * 64;
        #pragma unroll
        for (int i = 0; i < 4; i++) {
            int r = sr + 32 * i;
            CP16(smem_u32(As + r * HS + sc8),
                 A + (long)(bm + r) * K + k0 + sc8);
            CP16(smem_u32(Bs + r * HS + sc8),
                 Bt + (long)(bn + r) * K + k0 + sc8);
        }
        CP_COMMIT();
    };

    issue(0, 0);
    for (int kt = 0; kt < NK; kt++) {
        const int buf = kt & 1;
        if (kt + 1 < NK) { issue(kt + 1, buf ^ 1); CP_WAIT(1); }
        else             { CP_WAIT(0); }
        __syncthreads();

        const uint32_t a_buf = a_base0 + buf * 2 * HTILE * 2;
        const uint32_t b_buf = b_base0 + buf * 2 * HTILE * 2;
        #pragma unroll
        for (int ks = 0; ks < 4; ks++) {
            unsigned af[2][4];
            ldsm4(af[0][0], af[0][1], af[0][2], af[0][3], a_buf + ks * 32);
            ldsm4(af[1][0], af[1][1], af[1][2], af[1][3],
                  a_buf + 16 * HS * 2 + ks * 32);
            #pragma unroll
            for (int p = 0; p < 4; p++) {
                unsigned b0, b1, c0, c1;
                ldsm4(b0, b1, c0, c1, b_buf + p * 16 * HS * 2 + ks * 32);
                mma16(acc[0][2 * p],     af[0], b0, b1);
                mma16(acc[1][2 * p],     af[1], b0, b1);
                mma16(acc[0][2 * p + 1], af[0], c0, c1);
                mma16(acc[1][2 * p + 1], af[1], c0, c1);
            }
        }
        __syncthreads();
    }

    #pragma unroll
    for (int mt = 0; mt < 2; mt++) {
        const long r0 = bm + wm + mt * 16 + g;
        #pragma unroll
        for (int nt = 0; nt < 8; nt++) {
            const int col = bn + wn + nt * 8 + 2 * tq;
            const float bz0 = bias[col], bz1 = bias[col + 1];
            if (HALF_OUT) {
                __half* C = (__half*)Cout;
                __half2 v0 = __floats2half2_rn(acc[mt][nt][0] + bz0,
                                               acc[mt][nt][1] + bz1);
                __half2 v1 = __floats2half2_rn(acc[mt][nt][2] + bz0,
                                               acc[mt][nt][3] + bz1);
                *(__half2*)(C + r0 * N + col)       = v0;
                *(__half2*)(C + (r0 + 8) * N + col) = v1;
            } else {
                float* C = (float*)Cout;
                float2 v0 = { acc[mt][nt][0] + bz0, acc[mt][nt][1] + bz1 };
                float2 v1 = { acc[mt][nt][2] + bz0, acc[mt][nt][3] + bz1 };
                *(float2*)(C + r0 * N + col)       = v0;
                *(float2*)(C + (r0 + 8) * N + col) = v1;
            }
        }
    }
}

// ---------------------------------------------------------------------------
// Flash attention fp16: Br=128, Bc=64, 128 threads (4 warps), 3 CTAs/SM,
// DOUBLE-BUFFERED KV (issue t+1 after sync, before compute t).
// Smem (halves, stride 72): Q 128 | P 128 | K 2x64 | V 2x64 = 73728 B.
// ---------------------------------------------------------------------------
#define QS_OFF 0
#define PS_OFF (128 * HS)
#define KS_OFF (2 * 128 * HS)
#define VS_OFF (2 * 128 * HS + 2 * 64 * HS)
#define KVBUF (64 * HS)                              // halves per K or V buffer
#define FL_HALVES (2 * 128 * HS + 4 * 64 * HS)       // 36864 halves = 73728 B
#define NTILES (SEQ / 64)                            // 32

__global__ __launch_bounds__(128, 3) void flash_fp16()
{
    extern __shared__ __half fsm[];
    __half* Qs = fsm + QS_OFF;
    __half* Ps = fsm + PS_OFF;

    const int tid = threadIdx.x;
    const int lane = tid & 31, w = tid >> 5;
    const int g = lane >> 2, tq = lane & 3;
    const int b = blockIdx.y / NHEADS, h = blockIdx.y % NHEADS;
    const int q0 = blockIdx.x * 128;
    const long rowbase = (long)b * SEQ;
    const float kscale = 0.125f * 1.44269504089f;   // 1/sqrt(d) * log2(e)

    const uint32_t q_base = smem_u32(Qs) +
        ((w * 32 + (lane & 15)) * HS + (lane >> 4) * 8) * 2;
    const uint32_t p_base = smem_u32(Ps) +
        ((w * 32 + (lane & 15)) * HS + (lane >> 4) * 8) * 2;
    const uint32_t k_base = smem_u32(fsm + KS_OFF) +
        (((lane & 7) + (lane >> 4) * 8) * HS + ((lane >> 3) & 1) * 8) * 2;
    const uint32_t v_base = smem_u32(fsm + VS_OFF) +
        (((lane & 7) + ((lane >> 3) & 1) * 8) * HS + (lane >> 4) * 8) * 2;

    // Stage Q: 128 rows x 8 chunks of 8 halves (uint4), scale via f32.
    #pragma unroll
    for (int i = 0; i < 8; i++) {
        int idx = tid + 128 * i;
        int r = idx >> 3, c8 = (idx & 7) * 8;
        uint4 v = *(const uint4*)&g_qkv[(rowbase + q0 + r) * C3 + h * HD + c8];
        __half2* hp = (__half2*)&v;
        #pragma unroll
        for (int j = 0; j < 4; j++) {
            float2 f = __half22float2(hp[j]);
            hp[j] = __floats2half2_rn(f.x * kscale, f.y * kscale);
        }
        *(uint4*)(Qs + r * HS + c8) = v;
    }

    // KV staging: tile t into buffer bf
    auto issue_kv = [&](int t, int bf) {
        __half* Kd = fsm + KS_OFF + bf * KVBUF;
        __half* Vd = fsm + VS_OFF + bf * KVBUF;
        const int k0 = t * 64;
        #pragma unroll
        for (int i = 0; i < 4; i++) {
            int idx = tid + 128 * i;
            int r = idx >> 3, c8 = (idx & 7) * 8;
            long gb = (rowbase + k0 + r) * C3 + h * HD + c8;
            CP16(smem_u32(Kd + r * HS + c8), &g_qkv[gb + CH]);
            CP16(smem_u32(Vd + r * HS + c8), &g_qkv[gb + 2 * CH]);
        }
        CP_COMMIT();
    };

    float o[2][8][4];
    float m_i[2][2], l_i[2][2];
    #pragma unroll
    for (int mt = 0; mt < 2; mt++) {
        m_i[mt][0] = m_i[mt][1] = -1e30f;
        l_i[mt][0] = l_i[mt][1] = 0.f;
        #pragma unroll
        for (int nt = 0; nt < 8; nt++)
            #pragma unroll
            for (int j = 0; j < 4; j++) o[mt][nt][j] = 0.f;
    }

    issue_kv(0, 0);
    for (int t = 0; t < NTILES; t++) {
        const int buf = t & 1;
        CP_WAIT(0);            // KV(t) landed (only group in flight)
        __syncthreads();       // all warps done reading buf^1 (tile t-1)
        if (t + 1 < NTILES) issue_kv(t + 1, buf ^ 1);   // overlaps compute(t)

        const uint32_t k_buf = k_base + buf * KVBUF * 2;
        const uint32_t v_buf = v_base + buf * KVBUF * 2;

        // S = Q @ K^T  (4 x k16 over d=64)
        float s[2][8][4];
        #pragma unroll
        for (int mt = 0; mt < 2; mt++)
            #pragma unroll
            for (int nt = 0; nt < 8; nt++)
                #pragma unroll
                for (int j = 0; j < 4; j++) s[mt][nt][j] = 0.f;
        #pragma unroll
        for (int ks = 0; ks < 4; ks++) {
            unsigned af[2][4];
            ldsm4(af[0][0], af[0][1], af[0][2], af[0][3], q_base + ks * 32);
            ldsm4(af[1][0], af[1][1], af[1][2], af[1][3],
                  q_base + 16 * HS * 2 + ks * 32);
            #pragma unroll
            for (int p = 0; p < 4; p++) {
                unsigned b0, b1, c0, c1;
                ldsm4(b0, b1, c0, c1, k_buf + p * 16 * HS * 2 + ks * 32);
                mma16(s[0][2 * p],     af[0], b0, b1);
                mma16(s[1][2 * p],     af[1], b0, b1);
                mma16(s[0][2 * p + 1], af[0], c0, c1);
                mma16(s[1][2 * p + 1], af[1], c0, c1);
            }
        }

        // Online softmax (base-2) per 16-row sub-tile
        #pragma unroll
        for (int mt = 0; mt < 2; mt++) {
            float mx0 = -1e30f, mx1 = -1e30f;
            #pragma unroll
            for (int nt = 0; nt < 8; nt++) {
                mx0 = fmaxf(mx0, fmaxf(s[mt][nt][0], s[mt][nt][1]));
                mx1 = fmaxf(mx1, fmaxf(s[mt][nt][2], s[mt][nt][3]));
            }
            mx0 = fmaxf(mx0, __shfl_xor_sync(0xffffffffu, mx0, 1));
            mx0 = fmaxf(mx0, __shfl_xor_sync(0xffffffffu, mx0, 2));
            mx1 = fmaxf(mx1, __shfl_xor_sync(0xffffffffu, mx1, 1));
            mx1 = fmaxf(mx1, __shfl_xor_sync(0xffffffffu, mx1, 2));
            const float mn0 = fmaxf(m_i[mt][0], mx0), mn1 = fmaxf(m_i[mt][1], mx1);
            const float cr0 = exp2f(m_i[mt][0] - mn0), cr1 = exp2f(m_i[mt][1] - mn1);
            float rs0 = 0.f, rs1 = 0.f;
            #pragma unroll
            for (int nt = 0; nt < 8; nt++) {
                s[mt][nt][0] = exp2f(s[mt][nt][0] - mn0); rs0 += s[mt][nt][0];
                s[mt][nt][1] = exp2f(s[mt][nt][1] - mn0); rs0 += s[mt][nt][1];
                s[mt][nt][2] = exp2f(s[mt][nt][2] - mn1); rs1 += s[mt][nt][2];
                s[mt][nt][3] = exp2f(s[mt][nt][3] - mn1); rs1 += s[mt][nt][3];
            }
            rs0 += __shfl_xor_sync(0xffffffffu, rs0, 1);
            rs0 += __shfl_xor_sync(0xffffffffu, rs0, 2);
            rs1 += __shfl_xor_sync(0xffffffffu, rs1, 1);
            rs1 += __shfl_xor_sync(0xffffffffu, rs1, 2);
            l_i[mt][0] = l_i[mt][0] * cr0 + rs0;
            l_i[mt][1] = l_i[mt][1] * cr1 + rs1;
            m_i[mt][0] = mn0; m_i[mt][1] = mn1;
            #pragma unroll
            for (int nt = 0; nt < 8; nt++) {
                o[mt][nt][0] *= cr0; o[mt][nt][1] *= cr0;
                o[mt][nt][2] *= cr1; o[mt][nt][3] *= cr1;
            }
            const int pr = w * 32 + mt * 16 + g;
            #pragma unroll
            for (int nt = 0; nt < 8; nt++) {
                const int pc = nt * 8 + 2 * tq;
                *(__half2*)(Ps + pr * HS + pc) =
                    __floats2half2_rn(s[mt][nt][0], s[mt][nt][1]);
                *(__half2*)(Ps + (pr + 8) * HS + pc) =
                    __floats2half2_rn(s[mt][nt][2], s[mt][nt][3]);
            }
        }
        __syncwarp();

        // O += P @ V  (4 x k16 over kv=64; V via ldmatrix.trans)
        #pragma unroll
        for (int ks = 0; ks < 4; ks++) {
            unsigned af[2][4];
            ldsm4(af[0][0], af[0][1], af[0][2], af[0][3], p_base + ks * 32);
            ldsm4(af[1][0], af[1][1], af[1][2], af[1][3],
                  p_base + 16 * HS * 2 + ks * 32);
            #pragma unroll
            for (int p = 0; p < 4; p++) {
                unsigned b0, b1, c0, c1;
                ldsm4t(b0, b1, c0, c1,
                       v_buf + ks * 16 * HS * 2 + p * 16 * 2);
                mma16(o[0][2 * p],     af[0], b0, b1);
                mma16(o[1][2 * p],     af[1], b0, b1);
                mma16(o[0][2 * p + 1], af[0], c0, c1);
                mma16(o[1][2 * p + 1], af[1], c0, c1);
            }
        }
    }

    // Epilogue: normalize, store fp16 (feeds proj GEMM)
    #pragma unroll
    for (int mt = 0; mt < 2; mt++) {
        const float inv0 = 1.f / l_i[mt][0], inv1 = 1.f / l_i[mt][1];
        const long r0 = rowbase + q0 + w * 32 + mt * 16 + g;
        #pragma unroll
        for (int nt = 0; nt < 8; nt++) {
            const int col = h * HD + nt * 8 + 2 * tq;
            *(__half2*)(g_att + r0 * CH + col) =
                __floats2half2_rn(o[mt][nt][0] * inv0, o[mt][nt][1] * inv0);
            *(__half2*)(g_att + (r0 + 8) * CH + col) =
                __floats2half2_rn(o[mt][nt][2] * inv1, o[mt][nt][3] * inv1);
        }
    }
}

// ---------------------------------------------------------------------------
extern "C" void kernel_launch(void* const* d_in, const int* in_sizes, int n_in,
                              void* d_out, int out_size)
{
    const float* x     = (const float*)d_in[0];
    const float* Wqkv  = (const float*)d_in[1];
    const float* bqkv  = (const float*)d_in[2];
    const float* Wproj = (const float*)d_in[3];
    const float* bproj = (const float*)d_in[4];
    float* out = (float*)d_out;

    __half *xr, *qkv_ptr, *att_ptr, *wqkvT, *wprojT;
    cudaGetSymbolAddress((void**)&xr, g_x);
    cudaGetSymbolAddress((void**)&qkv_ptr, g_qkv);
    cudaGetSymbolAddress((void**)&att_ptr, g_att);
    cudaGetSymbolAddress((void**)&wqkvT, g_wqkvT);
    cudaGetSymbolAddress((void**)&wprojT, g_wprojT);

    static int smem_set = 0;
    const int gemm_smem  = 4 * HTILE * sizeof(__half);    // 73728 B
    const int flash_smem = FL_HALVES * sizeof(__half);    // 73728 B
    if (!smem_set) {
        cudaFuncSetAttribute(gemm_fp16<true>,
            cudaFuncAttributeMaxDynamicSharedMemorySize, gemm_smem);
        cudaFuncSetAttribute(gemm_fp16<false>,
            cudaFuncAttributeMaxDynamicSharedMemorySize, gemm_smem);
        cudaFuncSetAttribute(flash_fp16,
            cudaFuncAttributeMaxDynamicSharedMemorySize, flash_smem);
        smem_set = 1;
    }

    // Pre-round x to fp16; transpose weights to fp16
    round_kernel<<<(MTOT * CH) / 1024, 256>>>(x, xr);
    transpose_kernel<<<dim3(C3 / 32, CH / 32), 256>>>(Wqkv, wqkvT, CH, C3);
    transpose_kernel<<<dim3(CH / 32, CH / 32), 256>>>(Wproj, wprojT, CH, CH);

    // QKV projection (fp16 output)
    gemm_fp16<true><<<dim3(C3 / 128, MTOT / 128), 256, gemm_smem>>>(
        xr, wqkvT, bqkv, qkv_ptr, MTOT, C3, CH);
    // Flash attention (3 CTAs/SM, double-buffered KV)
    flash_fp16<<<dim3(SEQ / 128, BATCH * NHEADS), 128, flash_smem>>>();
    // Output projection (fp32 output)
    gemm_fp16<false><<<dim3(CH / 128, MTOT / 128), 256, gemm_smem>>>(
        att_ptr, wprojT, bproj, out, MTOT, CH, CH);
}

// round 11
// speedup vs baseline: 2.1107x; 1.0562x over previous
#include <cuda_runtime.h>
#include <cuda_fp16.h>
#include <cstdint>
#include <math.h>

#define BATCH 4
#define SEQ 2048
#define CH 768
#define NHEADS 12
#define HD 64
#define MTOT (BATCH * SEQ)   // 8192
#define C3 (3 * CH)          // 2304

// Scratch (allocation-free contract) — all fp16
__device__ __half g_x[(size_t)MTOT * CH];
__device__ __half g_qkv[(size_t)MTOT * C3];
__device__ __half g_att[(size_t)MTOT * CH];
__device__ __half g_wqkvT[(size_t)C3 * CH];
__device__ __half g_wprojT[(size_t)CH * CH];

__device__ __forceinline__ uint32_t smem_u32(const void* p) {
    uint32_t a;
    asm("{ .reg .u64 t; cvta.to.shared.u64 t, %1; cvt.u32.u64 %0, t; }"
        : "=r"(a) : "l"(p));
    return a;
}
#define CP16(dst, src) \
    asm volatile("cp.async.cg.shared.global [%0], [%1], 16;" \
                 :: "r"(dst), "l"(src) : "memory")
#define CP_COMMIT() asm volatile("cp.async.commit_group;" ::: "memory")
#define CP_WAIT(n)  asm volatile("cp.async.wait_group %0;" :: "n"(n) : "memory")

// m16n8k16 fp16 mma, fp32 accumulate in-place.
__device__ __forceinline__ void mma16(float* c, const unsigned* a,
                                      unsigned b0, unsigned b1) {
    asm volatile(
        "mma.sync.aligned.m16n8k16.row.col.f32.f16.f16.f32 "
        "{%0,%1,%2,%3}, {%4,%5,%6,%7}, {%8,%9}, {%0,%1,%2,%3};"
        : "+f"(c[0]), "+f"(c[1]), "+f"(c[2]), "+f"(c[3])
        : "r"(a[0]), "r"(a[1]), "r"(a[2]), "r"(a[3]), "r"(b0), "r"(b1));
}
__device__ __forceinline__ void ldsm4(unsigned& r0, unsigned& r1,
                                      unsigned& r2, unsigned& r3,
                                      uint32_t addr) {
    asm volatile("ldmatrix.sync.aligned.m8n8.x4.shared.b16 {%0,%1,%2,%3}, [%4];"
                 : "=r"(r0), "=r"(r1), "=r"(r2), "=r"(r3) : "r"(addr));
}
__device__ __forceinline__ void ldsm4t(unsigned& r0, unsigned& r1,
                                       unsigned& r2, unsigned& r3,
                                       uint32_t addr) {
    asm volatile("ldmatrix.sync.aligned.m8n8.x4.trans.shared.b16 {%0,%1,%2,%3}, [%4];"
                 : "=r"(r0), "=r"(r1), "=r"(r2), "=r"(r3) : "r"(addr));
}
__device__ __forceinline__ unsigned packh2(float a, float b) {
    __half2 h = __floats2half2_rn(a, b);
    return *(unsigned*)&h;
}

// ---------------------------------------------------------------------------
// Prepass: round x to fp16
// ---------------------------------------------------------------------------
__global__ __launch_bounds__(256) void round_kernel(
    const float* __restrict__ in, __half* __restrict__ outp)
{
    const int idx = blockIdx.x * 256 + threadIdx.x;
    float4 v = ((const float4*)in)[idx];
    __half2 h0 = __floats2half2_rn(v.x, v.y);
    __half2 h1 = __floats2half2_rn(v.z, v.w);
    uint2 o = { *(unsigned*)&h0, *(unsigned*)&h1 };
    ((uint2*)outp)[idx] = o;
}

// ---------------------------------------------------------------------------
// Weight transpose to fp16: Wt[n][k] = half(W[k][n])
// ---------------------------------------------------------------------------
__global__ __launch_bounds__(256) void transpose_kernel(
    const float* __restrict__ W, __half* __restrict__ Wt, int R, int Cc)
{
    __shared__ float t[32][33];
    const int bx = blockIdx.x * 32, by = blockIdx.y * 32;
    const int x = threadIdx.x & 31, y4 = (threadIdx.x >> 5) * 4;
    #pragma unroll
    for (int j = 0; j < 4; j++)
        t[y4 + j][x] = W[(long)(by + y4 + j) * Cc + bx + x];
    __syncthreads();
    #pragma unroll
    for (int j = 0; j < 4; j++)
        Wt[(long)(bx + y4 + j) * R + by + x] = __float2half_rn(t[x][y4 + j]);
}

// ---------------------------------------------------------------------------
// fp16 mma.sync GEMM + bias (unchanged): C = A @ Bt^T + bias
// ---------------------------------------------------------------------------
#define HS 72
#define HTILE (128 * HS)   // halves per operand tile

template <bool HALF_OUT>
__global__ __launch_bounds__(256, 2) void gemm_fp16(
    const __half* __restrict__ A, const __half* __restrict__ Bt,
    const float* __restrict__ bias, void* __restrict__ Cout,
    int M, int N, int K)
{
    extern __shared__ __half hsm[];
    const int tid = threadIdx.x;
    const int lane = tid & 31, wid = tid >> 5;
    const int g = lane >> 2, tq = lane & 3;
    const int wm = (wid & 3) * 32, wn = (wid >> 2) * 64;
    const int bm = blockIdx.y * 128, bn = blockIdx.x * 128;
    const int sr = tid >> 3, sc8 = (tid & 7) * 8;

    const uint32_t sbase = smem_u32(hsm);
    const uint32_t a_base0 = sbase +
        ((wm + (lane & 15)) * HS + (lane >> 4) * 8) * 2;
    const uint32_t b_base0 = sbase + HTILE * 2 +
        ((wn + (lane & 7) + (lane >> 4) * 8) * HS + ((lane >> 3) & 1) * 8) * 2;

    float acc[2][8][4];
    #pragma unroll
    for (int mt = 0; mt < 2; mt++)
        #pragma unroll
        for (int nt = 0; nt < 8; nt++)
            #pragma unroll
            for (int j = 0; j < 4; j++) acc[mt][nt][j] = 0.f;

    const int NK = K / 64;
    auto issue = [&](int kt, int b) {
        __half* As = hsm + b * 2 * HTILE;
        __half* Bs = As + HTILE;
        const int k0 = kt * 64;
        #pragma unroll
        for (int i = 0; i < 4; i++) {
            int r = sr + 32 * i;
            CP16(smem_u32(As + r * HS + sc8),
                 A + (long)(bm + r) * K + k0 + sc8);
            CP16(smem_u32(Bs + r * HS + sc8),
                 Bt + (long)(bn + r) * K + k0 + sc8);
        }
        CP_COMMIT();
    };

    issue(0, 0);
    for (int kt = 0; kt < NK; kt++) {
        const int buf = kt & 1;
        if (kt + 1 < NK) { issue(kt + 1, buf ^ 1); CP_WAIT(1); }
        else             { CP_WAIT(0); }
        __syncthreads();

        const uint32_t a_buf = a_base0 + buf * 2 * HTILE * 2;
        const uint32_t b_buf = b_base0 + buf * 2 * HTILE * 2;
        #pragma unroll
        for (int ks = 0; ks < 4; ks++) {
            unsigned af[2][4];
            ldsm4(af[0][0], af[0][1], af[0][2], af[0][3], a_buf + ks * 32);
            ldsm4(af[1][0], af[1][1], af[1][2], af[1][3],
                  a_buf + 16 * HS * 2 + ks * 32);
            #pragma unroll
            for (int p = 0; p < 4; p++) {
                unsigned b0, b1, c0, c1;
                ldsm4(b0, b1, c0, c1, b_buf + p * 16 * HS * 2 + ks * 32);
                mma16(acc[0][2 * p],     af[0], b0, b1);
                mma16(acc[1][2 * p],     af[1], b0, b1);
                mma16(acc[0][2 * p + 1], af[0], c0, c1);
                mma16(acc[1][2 * p + 1], af[1], c0, c1);
            }
        }
        __syncthreads();
    }

    #pragma unroll
    for (int mt = 0; mt < 2; mt++) {
        const long r0 = bm + wm + mt * 16 + g;
        #pragma unroll
        for (int nt = 0; nt < 8; nt++) {
            const int col = bn + wn + nt * 8 + 2 * tq;
            const float bz0 = bias[col], bz1 = bias[col + 1];
            if (HALF_OUT) {
                __half* C = (__half*)Cout;
                __half2 v0 = __floats2half2_rn(acc[mt][nt][0] + bz0,
                                               acc[mt][nt][1] + bz1);
                __half2 v1 = __floats2half2_rn(acc[mt][nt][2] + bz0,
                                               acc[mt][nt][3] + bz1);
                *(__half2*)(C + r0 * N + col)       = v0;
                *(__half2*)(C + (r0 + 8) * N + col) = v1;
            } else {
                float* C = (float*)Cout;
                float2 v0 = { acc[mt][nt][0] + bz0, acc[mt][nt][1] + bz1 };
                float2 v1 = { acc[mt][nt][2] + bz0, acc[mt][nt][3] + bz1 };
                *(float2*)(C + r0 * N + col)       = v0;
                *(float2*)(C + (r0 + 8) * N + col) = v1;
            }
        }
    }
}

// ---------------------------------------------------------------------------
// Flash attention fp16: Br=128, Bc=64, 128 threads (4 warps), 3 CTAs/SM,
// double-buffered KV, and P KEPT IN REGISTERS: the S C-fragment is repacked
// (half2) directly into the PV A-fragment — no P smem, no syncwarp.
// Smem (halves, stride 72): Q 128 | K 2x64 | V 2x64 = 55296 B.
// ---------------------------------------------------------------------------
#define QS_OFF 0
#define KS_OFF (128 * HS)
#define VS_OFF (128 * HS + 2 * 64 * HS)
#define KVBUF (64 * HS)                          // halves per K or V buffer
#define FL_HALVES (128 * HS + 4 * 64 * HS)       // 27648 halves = 55296 B
#define NTILES (SEQ / 64)                        // 32

__global__ __launch_bounds__(128, 3) void flash_fp16()
{
    extern __shared__ __half fsm[];
    __half* Qs = fsm + QS_OFF;

    const int tid = threadIdx.x;
    const int lane = tid & 31, w = tid >> 5;
    const int g = lane >> 2, tq = lane & 3;
    const int b = blockIdx.y / NHEADS, h = blockIdx.y % NHEADS;
    const int q0 = blockIdx.x * 128;
    const long rowbase = (long)b * SEQ;
    const float kscale = 0.125f * 1.44269504089f;   // 1/sqrt(d) * log2(e)

    const uint32_t q_base = smem_u32(Qs) +
        ((w * 32 + (lane & 15)) * HS + (lane >> 4) * 8) * 2;
    const uint32_t k_base = smem_u32(fsm + KS_OFF) +
        (((lane & 7) + (lane >> 4) * 8) * HS + ((lane >> 3) & 1) * 8) * 2;
    const uint32_t v_base = smem_u32(fsm + VS_OFF) +
        (((lane & 7) + ((lane >> 3) & 1) * 8) * HS + (lane >> 4) * 8) * 2;

    // Stage Q: 128 rows x 8 chunks of 8 halves (uint4), scale via f32.
    #pragma unroll
    for (int i = 0; i < 8; i++) {
        int idx = tid + 128 * i;
        int r = idx >> 3, c8 = (idx & 7) * 8;
        uint4 v = *(const uint4*)&g_qkv[(rowbase + q0 + r) * C3 + h * HD + c8];
        __half2* hp = (__half2*)&v;
        #pragma unroll
        for (int j = 0; j < 4; j++) {
            float2 f = __half22float2(hp[j]);
            hp[j] = __floats2half2_rn(f.x * kscale, f.y * kscale);
        }
        *(uint4*)(Qs + r * HS + c8) = v;
    }

    // KV staging: tile t into buffer bf
    auto issue_kv = [&](int t, int bf) {
        __half* Kd = fsm + KS_OFF + bf * KVBUF;
        __half* Vd = fsm + VS_OFF + bf * KVBUF;
        const int k0 = t * 64;
        #pragma unroll
        for (int i = 0; i < 4; i++) {
            int idx = tid + 128 * i;
            int r = idx >> 3, c8 = (idx & 7) * 8;
            long gb = (rowbase + k0 + r) * C3 + h * HD + c8;
            CP16(smem_u32(Kd + r * HS + c8), &g_qkv[gb + CH]);
            CP16(smem_u32(Vd + r * HS + c8), &g_qkv[gb + 2 * CH]);
        }
        CP_COMMIT();
    };

    float o[2][8][4];
    float m_i[2][2], l_i[2][2];
    #pragma unroll
    for (int mt = 0; mt < 2; mt++) {
        m_i[mt][0] = m_i[mt][1] = -1e30f;
        l_i[mt][0] = l_i[mt][1] = 0.f;
        #pragma unroll
        for (int nt = 0; nt < 8; nt++)
            #pragma unroll
            for (int j = 0; j < 4; j++) o[mt][nt][j] = 0.f;
    }

    issue_kv(0, 0);
    for (int t = 0; t < NTILES; t++) {
        const int buf = t & 1;
        CP_WAIT(0);            // KV(t) landed
        __syncthreads();       // all warps done reading buf^1 (tile t-1)
        if (t + 1 < NTILES) issue_kv(t + 1, buf ^ 1);   // overlaps compute(t)

        const uint32_t k_buf = k_base + buf * KVBUF * 2;
        const uint32_t v_buf = v_base + buf * KVBUF * 2;

        // S = Q @ K^T  (4 x k16 over d=64)
        float s[2][8][4];
        #pragma unroll
        for (int mt = 0; mt < 2; mt++)
            #pragma unroll
            for (int nt = 0; nt < 8; nt++)
                #pragma unroll
                for (int j = 0; j < 4; j++) s[mt][nt][j] = 0.f;
        #pragma unroll
        for (int ks = 0; ks < 4; ks++) {
            unsigned af[2][4];
            ldsm4(af[0][0], af[0][1], af[0][2], af[0][3], q_base + ks * 32);
            ldsm4(af[1][0], af[1][1], af[1][2], af[1][3],
                  q_base + 16 * HS * 2 + ks * 32);
            #pragma unroll
            for (int p = 0; p < 4; p++) {
                unsigned b0, b1, c0, c1;
                ldsm4(b0, b1, c0, c1, k_buf + p * 16 * HS * 2 + ks * 32);
                mma16(s[0][2 * p],     af[0], b0, b1);
                mma16(s[1][2 * p],     af[1], b0, b1);
                mma16(s[0][2 * p + 1], af[0], c0, c1);
                mma16(s[1][2 * p + 1], af[1], c0, c1);
            }
        }

        // Online softmax (base-2); pack exp2 results directly into PV A-frags
        unsigned pa[2][4][4];   // [mt][k16-step][frag]
        #pragma unroll
        for (int mt = 0; mt < 2; mt++) {
            float mx0 = -1e30f, mx1 = -1e30f;
            #pragma unroll
            for (int nt = 0; nt < 8; nt++) {
                mx0 = fmaxf(mx0, fmaxf(s[mt][nt][0], s[mt][nt][1]));
                mx1 = fmaxf(mx1, fmaxf(s[mt][nt][2], s[mt][nt][3]));
            }
            mx0 = fmaxf(mx0, __shfl_xor_sync(0xffffffffu, mx0, 1));
            mx0 = fmaxf(mx0, __shfl_xor_sync(0xffffffffu, mx0, 2));
            mx1 = fmaxf(mx1, __shfl_xor_sync(0xffffffffu, mx1, 1));
            mx1 = fmaxf(mx1, __shfl_xor_sync(0xffffffffu, mx1, 2));
            const float mn0 = fmaxf(m_i[mt][0], mx0), mn1 = fmaxf(m_i[mt][1], mx1);
            const float cr0 = exp2f(m_i[mt][0] - mn0), cr1 = exp2f(m_i[mt][1] - mn1);
            float rs0 = 0.f, rs1 = 0.f;
            #pragma unroll
            for (int j = 0; j < 4; j++) {      // k16 step = nt pair (2j, 2j+1)
                float e00 = exp2f(s[mt][2*j][0] - mn0);
                float e01 = exp2f(s[mt][2*j][1] - mn0);
                float e02 = exp2f(s[mt][2*j][2] - mn1);
                float e03 = exp2f(s[mt][2*j][3] - mn1);
                float e10 = exp2f(s[mt][2*j+1][0] - mn0);
                float e11 = exp2f(s[mt][2*j+1][1] - mn0);
                float e12 = exp2f(s[mt][2*j+1][2] - mn1);
                float e13 = exp2f(s[mt][2*j+1][3] - mn1);
                rs0 += (e00 + e01) + (e10 + e11);
                rs1 += (e02 + e03) + (e12 + e13);
                pa[mt][j][0] = packh2(e00, e01);
                pa[mt][j][1] = packh2(e02, e03);
                pa[mt][j][2] = packh2(e10, e11);
                pa[mt][j][3] = packh2(e12, e13);
            }
            rs0 += __shfl_xor_sync(0xffffffffu, rs0, 1);
            rs0 += __shfl_xor_sync(0xffffffffu, rs0, 2);
            rs1 += __shfl_xor_sync(0xffffffffu, rs1, 1);
            rs1 += __shfl_xor_sync(0xffffffffu, rs1, 2);
            l_i[mt][0] = l_i[mt][0] * cr0 + rs0;
            l_i[mt][1] = l_i[mt][1] * cr1 + rs1;
            m_i[mt][0] = mn0; m_i[mt][1] = mn1;
            #pragma unroll
            for (int nt = 0; nt < 8; nt++) {
                o[mt][nt][0] *= cr0; o[mt][nt][1] *= cr0;
                o[mt][nt][2] *= cr1; o[mt][nt][3] *= cr1;
            }
        }

        // O += P @ V  (P from registers; V via ldmatrix.trans)
        #pragma unroll
        for (int ks = 0; ks < 4; ks++) {
            #pragma unroll
            for (int p = 0; p < 4; p++) {
                unsigned b0, b1, c0, c1;
                ldsm4t(b0, b1, c0, c1,
                       v_buf + ks * 16 * HS * 2 + p * 16 * 2);
                mma16(o[0][2 * p],     pa[0][ks], b0, b1);
                mma16(o[1][2 * p],     pa[1][ks], b0, b1);
                mma16(o[0][2 * p + 1], pa[0][ks], c0, c1);
                mma16(o[1][2 * p + 1], pa[1][ks], c0, c1);
            }
        }
    }

    // Epilogue: normalize, store fp16 (feeds proj GEMM)
    #pragma unroll
    for (int mt = 0; mt < 2; mt++) {
        const float inv0 = 1.f / l_i[mt][0], inv1 = 1.f / l_i[mt][1];
        const long r0 = rowbase + q0 + w * 32 + mt * 16 + g;
        #pragma unroll
        for (int nt = 0; nt < 8; nt++) {
            const int col = h * HD + nt * 8 + 2 * tq;
            *(__half2*)(g_att + r0 * CH + col) =
                __floats2half2_rn(o[mt][nt][0] * inv0, o[mt][nt][1] * inv0);
            *(__half2*)(g_att + (r0 + 8) * CH + col) =
                __floats2half2_rn(o[mt][nt][2] * inv1, o[mt][nt][3] * inv1);
        }
    }
}

// ---------------------------------------------------------------------------
extern "C" void kernel_launch(void* const* d_in, const int* in_sizes, int n_in,
                              void* d_out, int out_size)
{
    const float* x     = (const float*)d_in[0];
    const float* Wqkv  = (const float*)d_in[1];
    const float* bqkv  = (const float*)d_in[2];
    const float* Wproj = (const float*)d_in[3];
    const float* bproj = (const float*)d_in[4];
    float* out = (float*)d_out;

    __half *xr, *qkv_ptr, *att_ptr, *wqkvT, *wprojT;
    cudaGetSymbolAddress((void**)&xr, g_x);
    cudaGetSymbolAddress((void**)&qkv_ptr, g_qkv);
    cudaGetSymbolAddress((void**)&att_ptr, g_att);
    cudaGetSymbolAddress((void**)&wqkvT, g_wqkvT);
    cudaGetSymbolAddress((void**)&wprojT, g_wprojT);

    static int smem_set = 0;
    const int gemm_smem  = 4 * HTILE * sizeof(__half);    // 73728 B
    const int flash_smem = FL_HALVES * sizeof(__half);    // 55296 B
    if (!smem_set) {
        cudaFuncSetAttribute(gemm_fp16<true>,
            cudaFuncAttributeMaxDynamicSharedMemorySize, gemm_smem);
        cudaFuncSetAttribute(gemm_fp16<false>,
            cudaFuncAttributeMaxDynamicSharedMemorySize, gemm_smem);
        cudaFuncSetAttribute(flash_fp16,
            cudaFuncAttributeMaxDynamicSharedMemorySize, flash_smem);
        smem_set = 1;
    }

    // Pre-round x to fp16; transpose weights to fp16
    round_kernel<<<(MTOT * CH) / 1024, 256>>>(x, xr);
    transpose_kernel<<<dim3(C3 / 32, CH / 32), 256>>>(Wqkv, wqkvT, CH, C3);
    transpose_kernel<<<dim3(CH / 32, CH / 32), 256>>>(Wproj, wprojT, CH, CH);

    // QKV projection (fp16 output)
    gemm_fp16<true><<<dim3(C3 / 128, MTOT / 128), 256, gemm_smem>>>(
        xr, wqkvT, bqkv, qkv_ptr, MTOT, C3, CH);
    // Flash attention (3 CTAs/SM, double-buffered KV, P in registers)
    flash_fp16<<<dim3(SEQ / 128, BATCH * NHEADS), 128, flash_smem>>>();
    // Output projection (fp32 output)
    gemm_fp16<false><<<dim3(CH / 128, MTOT / 128), 256, gemm_smem>>>(
        att_ptr, wprojT, bproj, out, MTOT, CH, CH);
}